// round 15
// baseline (speedup 1.0000x reference)
#include <cuda_runtime.h>
#include <cuda_fp16.h>
#include <cstdint>

// GCNConv: 3x [BatchNorm -> GraphConv(norm=both) -> ReLU], N=10000 E=160000 D=512
// R14 == R11 resubmit (GB300 container infra failure twice; kernel never ran):
//   fp16 hi/lo split; cross terms via f16-accumulate MMAs (rate experiment);
//   launch count 18 -> 12 (detect->prep, norm->scan, bn_final->aggregate,
//   BN stats ping-pong buffers).

#define D 512
#define D4 128
#define NMAX 10240
#define EMAX 200000
#define BPAD 40   // SMEM row stride (elems); 80B rows -> ldmatrix conflict-free

__device__ float g_x[(size_t)NMAX * D];
__device__ __half g_ahi[(size_t)NMAX * D];
__device__ __half g_alo[(size_t)NMAX * D];
__device__ __half g_bhi[(size_t)3 * D * D];   // transposed: [l][n][k]
__device__ __half g_blo[(size_t)3 * D * D];
__device__ float g_srcnorm[NMAX];
__device__ float g_dstnorm[NMAX];
__device__ int   g_src[EMAX];
__device__ int   g_dst[EMAX];
__device__ int   g_outdeg[NMAX];
__device__ int   g_indeg[NMAX];
__device__ int   g_cursor[NMAX];
__device__ int   g_rowoff[NMAX + 1];
__device__ int   g_csr[EMAX];
__device__ float g_ssum[2][D];   // BN stats ping-pong
__device__ float g_ssq[2][D];

// ------------------------------------------------------------ ptx helpers

__device__ __forceinline__ uint32_t smem_u32(const void* p) {
    uint32_t a;
    asm("{ .reg .u64 t; cvta.to.shared.u64 t, %1; cvt.u32.u64 %0, t; }"
        : "=r"(a) : "l"(p));
    return a;
}
#define LDSM_X4(r, addr) \
    asm volatile("ldmatrix.sync.aligned.m8n8.x4.shared.b16 {%0,%1,%2,%3}, [%4];" \
        : "=r"((r)[0]), "=r"((r)[1]), "=r"((r)[2]), "=r"((r)[3]) : "r"(addr))
#define LDSM_X2(r, addr) \
    asm volatile("ldmatrix.sync.aligned.m8n8.x2.shared.b16 {%0,%1}, [%2];" \
        : "=r"((r)[0]), "=r"((r)[1]) : "r"(addr))
// main term: f16 inputs, f32 accumulate
#define MMA_F32ACC(d, a, b) \
    asm volatile("mma.sync.aligned.m16n8k16.row.col.f32.f16.f16.f32 " \
        "{%0,%1,%2,%3}, {%4,%5,%6,%7}, {%8,%9}, {%0,%1,%2,%3};" \
        : "+f"((d)[0]), "+f"((d)[1]), "+f"((d)[2]), "+f"((d)[3]) \
        : "r"((a)[0]), "r"((a)[1]), "r"((a)[2]), "r"((a)[3]), \
          "r"((b)[0]), "r"((b)[1]))
// cross terms: f16 inputs, f16 accumulate (packed f16x2 d-regs)
#define MMA_F16ACC(d, a, b) \
    asm volatile("mma.sync.aligned.m16n8k16.row.col.f16.f16.f16.f16 " \
        "{%0,%1}, {%2,%3,%4,%5}, {%6,%7}, {%0,%1};" \
        : "+r"((d)[0]), "+r"((d)[1]) \
        : "r"((a)[0]), "r"((a)[1]), "r"((a)[2]), "r"((a)[3]), \
          "r"((b)[0]), "r"((b)[1]))
#define CP16(saddr, gptr) \
    asm volatile("cp.async.cg.shared.global [%0], [%1], 16;" \
                 :: "r"(saddr), "l"(gptr) : "memory")
#define CP_COMMIT() asm volatile("cp.async.commit_group;" ::: "memory")
#define CP_WAIT(n)  asm volatile("cp.async.wait_group %0;" :: "n"(n) : "memory")

// ------------------------------------------------------------ prep

// detect dtype (per-block, redundant), zero counters + stats, convert indices
__global__ void prep_kernel(const void* __restrict__ srcp,
                            const void* __restrict__ dstp, int E, int N) {
    __shared__ int s_is64;
    if (threadIdx.x == 0) {
        const int* p = (const int*)srcp;
        int all0 = 1;
        for (int i = 1; i < 128; i += 2)
            if (p[i] != 0) { all0 = 0; break; }
        s_is64 = all0;
    }
    __syncthreads();
    int e = blockIdx.x * blockDim.x + threadIdx.x;
    if (e < N) { g_outdeg[e] = 0; g_indeg[e] = 0; g_cursor[e] = 0; }
    if (e < 2 * D) { ((float*)g_ssum)[e] = 0.f; ((float*)g_ssq)[e] = 0.f; }
    if (e >= E) return;
    int s, d;
    if (s_is64) {
        s = (int)((const long long*)srcp)[e];
        d = (int)((const long long*)dstp)[e];
    } else {
        s = ((const int*)srcp)[e];
        d = ((const int*)dstp)[e];
    }
    s = min(max(s, 0), N - 1);
    d = min(max(d, 0), N - 1);
    g_src[e] = s;
    g_dst[e] = d;
}

__global__ void degree_kernel(int E) {
    int e = blockIdx.x * blockDim.x + threadIdx.x;
    if (e < E) {
        atomicAdd(&g_outdeg[g_src[e]], 1);
        atomicAdd(&g_indeg[g_dst[e]], 1);
    }
}

// prefix sum of in-degree -> row offsets; also computes src/dst norms
__global__ void scan_kernel(int N) {
    __shared__ int warp_sums[32];
    int tid = threadIdx.x, lane = tid & 31, wid = tid >> 5;
    int chunk = (N + 1023) / 1024;
    int start = tid * chunk;
    int end = start + chunk; if (end > N) end = N;
    int s = 0;
    for (int i = start; i < end; i++) s += g_indeg[i];
    int v = s;
    #pragma unroll
    for (int o = 1; o < 32; o <<= 1) {
        int t = __shfl_up_sync(0xFFFFFFFFu, v, o);
        if (lane >= o) v += t;
    }
    if (lane == 31) warp_sums[wid] = v;
    __syncthreads();
    if (wid == 0) {
        int w = warp_sums[lane];
        #pragma unroll
        for (int o = 1; o < 32; o <<= 1) {
            int t = __shfl_up_sync(0xFFFFFFFFu, w, o);
            if (lane >= o) w += t;
        }
        warp_sums[lane] = w;
    }
    __syncthreads();
    int excl = (v - s) + (wid > 0 ? warp_sums[wid - 1] : 0);
    int run = excl;
    for (int i = start; i < end; i++) {
        g_rowoff[i] = run;
        run += g_indeg[i];
        int od = g_outdeg[i]; if (od < 1) od = 1;
        int id = g_indeg[i];  if (id < 1) id = 1;
        g_srcnorm[i] = rsqrtf((float)od);
        g_dstnorm[i] = rsqrtf((float)id);
    }
    if (start < N && end == N) g_rowoff[N] = run;
}

__global__ void csr_fill_kernel(int E) {
    int e = blockIdx.x * blockDim.x + threadIdx.x;
    if (e < E) {
        int d = g_dst[e];
        int p = atomicAdd(&g_cursor[d], 1);
        g_csr[g_rowoff[d] + p] = g_src[e];
    }
}

// layer-0 BN stats over external input x -> buffer 0
__global__ void bn_stats_kernel(const float* __restrict__ x, int N) {
    int t = threadIdx.x;
    float s0 = 0.f, q0 = 0.f, s1 = 0.f, q1 = 0.f;
    for (int r = blockIdx.x; r < N; r += gridDim.x) {
        float v0 = x[(size_t)r * D + t];
        float v1 = x[(size_t)r * D + t + 256];
        s0 += v0; q0 += v0 * v0;
        s1 += v1; q1 += v1 * v1;
    }
    atomicAdd(&g_ssum[0][t],       s0);
    atomicAdd(&g_ssq[0][t],        q0);
    atomicAdd(&g_ssum[0][t + 256], s1);
    atomicAdd(&g_ssq[0][t + 256],  q1);
}

// ----------------------------------------------------- W transpose + split

__global__ void wsplit_kernel(const float* __restrict__ W) {
    __shared__ float tile[32][33];
    int l = blockIdx.z;
    int kb = blockIdx.x * 32, nb = blockIdx.y * 32;
    int tx = threadIdx.x, ty = threadIdx.y;   // 32 x 8
    const float* Wl = W + (size_t)l * D * D;
    #pragma unroll
    for (int i = 0; i < 32; i += 8)
        tile[ty + i][tx] = Wl[(size_t)(kb + ty + i) * D + nb + tx];
    __syncthreads();
    size_t off = (size_t)l * D * D;
    #pragma unroll
    for (int i = 0; i < 32; i += 8) {
        float v = tile[tx][ty + i];
        __half hi = __float2half(v);
        __half lo = __float2half(v - __half2float(hi));
        size_t idx = off + (size_t)(nb + ty + i) * D + kb + tx;
        g_bhi[idx] = hi;
        g_blo[idx] = lo;
    }
}

// -------- aggregation (BN scale/shift computed inline, emits fp16 hi/lo)

__global__ void aggregate_kernel(const float* __restrict__ x_ext,
                                 const float* __restrict__ gamma,
                                 const float* __restrict__ beta,
                                 float invN, int layer, int N) {
    int node = blockIdx.x;                 // grid = NPAD (rows >= N are zero)
    int t = threadIdx.x;                   // 128 threads x 4 cols
    int sbuf = layer & 1, zbuf = sbuf ^ 1;

    // blocks 0..7 zero the OTHER stats buffer (consumed; gemm refills it)
    if (node < 8) {
        int j = node * 64 + (t >> 1);
        if (t & 1) { g_ssq[zbuf][j] = 0.f; }
        else       { g_ssum[zbuf][j] = 0.f; }
    }

    __half hv[4], lv[4];
    if (node >= N) {
        #pragma unroll
        for (int c = 0; c < 4; c++) { hv[c] = __float2half(0.f); lv[c] = hv[c]; }
        *(uint2*)&g_ahi[(size_t)node * D + t * 4] = *(uint2*)hv;
        *(uint2*)&g_alo[(size_t)node * D + t * 4] = *(uint2*)lv;
        return;
    }

    // BN scale/shift for this thread's 4 columns (identical across blocks)
    float sc[4], sh[4];
    #pragma unroll
    for (int c = 0; c < 4; c++) {
        int j = t * 4 + c;
        float mu  = g_ssum[sbuf][j] * invN;
        float var = g_ssq[sbuf][j] * invN - mu * mu;
        float s   = rsqrtf(var + 1e-5f) * gamma[j];
        sc[c] = s;
        sh[c] = beta[j] - mu * s;
    }

    const float4* __restrict__ x4 =
        (const float4*)(x_ext ? x_ext : (const float*)g_x);
    int e0 = g_rowoff[node], e1 = g_rowoff[node + 1];
    float4 acc0 = make_float4(0.f, 0.f, 0.f, 0.f);
    float4 acc1 = make_float4(0.f, 0.f, 0.f, 0.f);
    int e = e0;
    for (; e + 1 < e1; e += 2) {
        int s0 = g_csr[e], s1 = g_csr[e + 1];
        float n0 = __ldg(&g_srcnorm[s0]);
        float n1 = __ldg(&g_srcnorm[s1]);
        float4 v0 = x4[(size_t)s0 * D4 + t];
        float4 v1 = x4[(size_t)s1 * D4 + t];
        acc0.x += (v0.x * sc[0] + sh[0]) * n0;
        acc0.y += (v0.y * sc[1] + sh[1]) * n0;
        acc0.z += (v0.z * sc[2] + sh[2]) * n0;
        acc0.w += (v0.w * sc[3] + sh[3]) * n0;
        acc1.x += (v1.x * sc[0] + sh[0]) * n1;
        acc1.y += (v1.y * sc[1] + sh[1]) * n1;
        acc1.z += (v1.z * sc[2] + sh[2]) * n1;
        acc1.w += (v1.w * sc[3] + sh[3]) * n1;
    }
    if (e < e1) {
        int s0 = g_csr[e];
        float n0 = __ldg(&g_srcnorm[s0]);
        float4 v0 = x4[(size_t)s0 * D4 + t];
        acc0.x += (v0.x * sc[0] + sh[0]) * n0;
        acc0.y += (v0.y * sc[1] + sh[1]) * n0;
        acc0.z += (v0.z * sc[2] + sh[2]) * n0;
        acc0.w += (v0.w * sc[3] + sh[3]) * n0;
    }
    float dn = g_dstnorm[node];
    float a[4] = {(acc0.x + acc1.x) * dn, (acc0.y + acc1.y) * dn,
                  (acc0.z + acc1.z) * dn, (acc0.w + acc1.w) * dn};
    #pragma unroll
    for (int c = 0; c < 4; c++) {
        hv[c] = __float2half(a[c]);
        lv[c] = __float2half(a[c] - __half2float(hv[c]));
    }
    *(uint2*)&g_ahi[(size_t)node * D + t * 4] = *(uint2*)hv;
    *(uint2*)&g_alo[(size_t)node * D + t * 4] = *(uint2*)lv;
}

// ------------------------------------------------ mma.sync GEMM (fp16x3)

// C = relu(A @ Bt^T + bias); CTA 128x64, 8 warps (4m x 2n), warp tile 32x32,
// BK=32, 2-stage cp.async. Main term f32-acc; both cross terms share f16-acc.
#define A_ST  (128 * BPAD)
#define B_ST  (64 * BPAD)
#define SM_ELEMS (2 * A_ST * 2 + 2 * B_ST * 2)
#define SM_BYTES (SM_ELEMS * 2)  // 61440

__global__ __launch_bounds__(256, 2)
void gemm_mma_kernel(int layer, const float* __restrict__ bias,
                     float* __restrict__ Cext, int M, int do_stats) {
    extern __shared__ char smraw[];
    __half* As_hi = (__half*)smraw;            // [2][A_ST]
    __half* As_lo = As_hi + 2 * A_ST;
    __half* Bs_hi = As_lo + 2 * A_ST;          // [2][B_ST]
    __half* Bs_lo = Bs_hi + 2 * B_ST;

    const __half* __restrict__ Bhi = g_bhi + (size_t)layer * D * D;
    const __half* __restrict__ Blo = g_blo + (size_t)layer * D * D;
    float* __restrict__ C = Cext ? Cext : g_x;
    int nbuf = (layer + 1) & 1;

    int tid = threadIdx.x;
    int lane = tid & 31;
    int wid = tid >> 5;
    int wm = wid & 3;
    int wn = wid >> 2;
    int m0 = blockIdx.x * 128, n0 = blockIdx.y * 64;

    float acc[2][4][4];
    uint32_t xacc[2][4][2];     // f16x2 cross accumulators
    #pragma unroll
    for (int i = 0; i < 2; i++)
        #pragma unroll
        for (int j = 0; j < 4; j++) {
            #pragma unroll
            for (int k = 0; k < 4; k++) acc[i][j][k] = 0.f;
            xacc[i][j][0] = 0u; xacc[i][j][1] = 0u;
        }

    int a_row = wm * 32 + (lane & 15);
    int a_col = (lane >> 4) * 8;
    int b_row = wn * 32 + (lane & 7);
    int b_col = ((lane >> 3) & 1) * 8;
    int la_row = tid >> 2, la_seg = tid & 3;

    #define ISSUE_LOADS(kc, buf) do {                                           \
        int _k0 = (kc) * 32;                                                    \
        int _ab = (buf) * A_ST, _bb = (buf) * B_ST;                             \
        _Pragma("unroll")                                                       \
        for (int _i = 0; _i < 2; _i++) {                                        \
            int _row = la_row + _i * 64;                                        \
            size_t _ga = (size_t)(m0 + _row) * D + _k0 + la_seg * 8;            \
            uint32_t _sa = smem_u32(&As_hi[_ab + _row * BPAD + la_seg * 8]);    \
            CP16(_sa, g_ahi + _ga);                                             \
            _sa = smem_u32(&As_lo[_ab + _row * BPAD + la_seg * 8]);             \
            CP16(_sa, g_alo + _ga);                                             \
        }                                                                       \
        {                                                                       \
            size_t _gb = (size_t)(n0 + la_row) * D + _k0 + la_seg * 8;          \
            uint32_t _sb = smem_u32(&Bs_hi[_bb + la_row * BPAD + la_seg * 8]);  \
            CP16(_sb, Bhi + _gb);                                               \
            _sb = smem_u32(&Bs_lo[_bb + la_row * BPAD + la_seg * 8]);           \
            CP16(_sb, Blo + _gb);                                               \
        }                                                                       \
        CP_COMMIT();                                                            \
    } while (0)

    ISSUE_LOADS(0, 0);

    for (int kc = 0; kc < 16; kc++) {
        if (kc < 15) { ISSUE_LOADS(kc + 1, (kc + 1) & 1); CP_WAIT(1); }
        else         { CP_WAIT(0); }
        __syncthreads();

        int ab = (kc & 1) * A_ST, bb = (kc & 1) * B_ST;
        #pragma unroll
        for (int ks = 0; ks < 32; ks += 16) {
            uint32_t ahi[2][4], alo[2][4], bfr[4][2];
            #pragma unroll
            for (int mi = 0; mi < 2; mi++) {
                uint32_t ad = smem_u32(&As_hi[ab + (a_row + mi * 16) * BPAD + a_col + ks]);
                LDSM_X4(ahi[mi], ad);
                ad = smem_u32(&As_lo[ab + (a_row + mi * 16) * BPAD + a_col + ks]);
                LDSM_X4(alo[mi], ad);
            }
            // B hi: main (f32 acc) + cross al*bh (f16 acc)
            #pragma unroll
            for (int ni = 0; ni < 4; ni++) {
                uint32_t bd = smem_u32(&Bs_hi[bb + (b_row + ni * 8) * BPAD + b_col + ks]);
                LDSM_X2(bfr[ni], bd);
            }
            #pragma unroll
            for (int mi = 0; mi < 2; mi++)
                #pragma unroll
                for (int ni = 0; ni < 4; ni++) {
                    MMA_F32ACC(acc[mi][ni], ahi[mi], bfr[ni]);
                    MMA_F16ACC(xacc[mi][ni], alo[mi], bfr[ni]);
                }
            // B lo: cross ah*bl (f16 acc, same accumulator)
            #pragma unroll
            for (int ni = 0; ni < 4; ni++) {
                uint32_t bd = smem_u32(&Bs_lo[bb + (b_row + ni * 8) * BPAD + b_col + ks]);
                LDSM_X2(bfr[ni], bd);
            }
            #pragma unroll
            for (int mi = 0; mi < 2; mi++)
                #pragma unroll
                for (int ni = 0; ni < 4; ni++)
                    MMA_F16ACC(xacc[mi][ni], ahi[mi], bfr[ni]);
        }
        __syncthreads();
    }

    // epilogue: combine cross terms, bias + relu + store (+ BN stats)
    float* cs = (float*)smraw;
    float* cq = cs + 64;
    if (do_stats) {
        if (tid < 64) { cs[tid] = 0.f; cq[tid] = 0.f; }
        __syncthreads();
    }

    int rbase = m0 + wm * 32 + (lane >> 2);
    int lcb   = wn * 32 + (lane & 3) * 2;
    #pragma unroll
    for (int ni = 0; ni < 4; ni++) {
        int lc = lcb + ni * 8;
        int c  = n0 + lc;
        float b0 = bias[c], b1 = bias[c + 1];
        float sx = 0.f, sy = 0.f, qx = 0.f, qy = 0.f;
        #pragma unroll
        for (int mi = 0; mi < 2; mi++) {
            __half2 x0 = *(__half2*)&xacc[mi][ni][0];
            __half2 x1 = *(__half2*)&xacc[mi][ni][1];
            int r0 = rbase + mi * 16;
            if (r0 < M) {
                float2 o;
                o.x = fmaxf(acc[mi][ni][0] + __half2float(x0.x) + b0, 0.f);
                o.y = fmaxf(acc[mi][ni][1] + __half2float(x0.y) + b1, 0.f);
                *(float2*)&C[(size_t)r0 * D + c] = o;
                sx += o.x; qx += o.x * o.x;
                sy += o.y; qy += o.y * o.y;
            }
            int r1 = r0 + 8;
            if (r1 < M) {
                float2 o;
                o.x = fmaxf(acc[mi][ni][2] + __half2float(x1.x) + b0, 0.f);
                o.y = fmaxf(acc[mi][ni][3] + __half2float(x1.y) + b1, 0.f);
                *(float2*)&C[(size_t)r1 * D + c] = o;
                sx += o.x; qx += o.x * o.x;
                sy += o.y; qy += o.y * o.y;
            }
        }
        if (do_stats) {
            atomicAdd(&cs[lc], sx);     atomicAdd(&cq[lc], qx);
            atomicAdd(&cs[lc + 1], sy); atomicAdd(&cq[lc + 1], qy);
        }
    }
    if (do_stats) {
        __syncthreads();
        if (tid < 64) {
            atomicAdd(&g_ssum[nbuf][n0 + tid], cs[tid]);
            atomicAdd(&g_ssq[nbuf][n0 + tid],  cq[tid]);
        }
    }
}

// ---------------------------------------------------------------- launch

extern "C" void kernel_launch(void* const* d_in, const int* in_sizes, int n_in,
                              void* d_out, int out_size) {
    const float* x     = (const float*)d_in[0];
    const void*  src   = d_in[1];
    const void*  dst   = d_in[2];
    const float* gamma = (const float*)d_in[3];
    const float* beta  = (const float*)d_in[4];
    const float* W     = (const float*)d_in[5];
    const float* b     = (const float*)d_in[6];

    int N = in_sizes[0] / D;
    int E = in_sizes[1];
    int L = in_sizes[3] / D;
    int NPAD = ((N + 127) / 128) * 128;
    float invN = 1.0f / (float)N;

    cudaFuncSetAttribute(gemm_mma_kernel,
                         cudaFuncAttributeMaxDynamicSharedMemorySize, SM_BYTES);

    prep_kernel<<<(E + 255) / 256, 256>>>(src, dst, E, N);
    degree_kernel<<<(E + 255) / 256, 256>>>(E);
    scan_kernel<<<1, 1024>>>(N);
    csr_fill_kernel<<<(E + 255) / 256, 256>>>(E);
    bn_stats_kernel<<<256, 256>>>(x, N);
    wsplit_kernel<<<dim3(16, 16, (unsigned)L), dim3(32, 8)>>>(W);

    dim3 gemm_grid(NPAD / 128, D / 64);

    for (int l = 0; l < L; l++) {
        aggregate_kernel<<<NPAD, 128>>>((l == 0) ? x : nullptr,
                                        gamma + (size_t)l * D,
                                        beta + (size_t)l * D, invN, l, N);
        float* cext = (l == L - 1) ? (float*)d_out : nullptr;
        int do_stats = (l < L - 1) ? 1 : 0;
        gemm_mma_kernel<<<gemm_grid, 256, SM_BYTES>>>(
            l, b + (size_t)l * D, cext, N, do_stats);
    }
}